// round 5
// baseline (speedup 1.0000x reference)
#include <cuda_runtime.h>
#include <cuda_bf16.h>

// ---------------- problem constants ----------------
#define BATCH 32
#define KSAMP 16
#define D_IN  312
#define H1    1024
#define H2    2048
#define D_OUT 128
#define ROWS  17          // 1 query + 16 samples
#define ROWP  9           // row pairs (rows padded to 18; row 17 computed, never stored)
#define RPAD  20          // smem row stride in floats (80B -> 16B-aligned pair loads)
#define INV_T 8.3333333333333333f   // 1/0.12

// ---------------- decomposition ----------------
#define KCH1 3            // L1 K-split (chunks of 104)
#define CCH1 104
#define U1   4            // prefetch group (G = 26, even)
#define CB1  4            // L1 col blocks (128 thr x 2 cols = 256 cols each)
#define KCH2 4            // L2 K-split (chunks of 256)
#define CCH2 256
#define U2   8            // G = 32
#define CB2  8            // L2 col blocks
#define KCH3 16           // L3 K-split (chunks of 128)
#define CCH3 128
#define U3   8            // G = 16

typedef unsigned long long u64;

// ---------------- scratch (no allocations allowed) ----------------
__device__ float g_h1p[(size_t)KCH1 * BATCH * ROWS * H1];    // 6.7 MB  L1 partials
__device__ float g_h2p[(size_t)KCH2 * BATCH * ROWS * H2];    // 17.8 MB L2 partials
__device__ float g_p  [(size_t)KCH3 * BATCH * ROWS * D_OUT]; // 4.45 MB L3 partials
__device__ float g_qk [(size_t)BATCH * ROWS * D_OUT];        // 278 KB reduced L3 out

// ---------------- f32x2 helpers ----------------
__device__ __forceinline__ u64 pack2(float lo, float hi) {
    u64 r; asm("mov.b64 %0, {%1, %2};" : "=l"(r) : "f"(lo), "f"(hi)); return r;
}
__device__ __forceinline__ float2 unpack2(u64 v) {
    float2 f; asm("mov.b64 {%0, %1}, %2;" : "=f"(f.x), "=f"(f.y) : "l"(v)); return f;
}
__device__ __forceinline__ u64 ffma2(u64 a, u64 b, u64 c) {
    u64 d; asm("fma.rn.f32x2 %0, %1, %2, %3;" : "=l"(d) : "l"(a), "l"(b), "l"(c)); return d;
}

// ---------------- pipelined core building blocks ----------------
template<int U, int LDW>
__device__ __forceinline__ void ldg_w2(const float* __restrict__ Wp, int c0, float2 w[U]) {
#pragma unroll
    for (int i = 0; i < U; ++i)
        w[i] = __ldg(reinterpret_cast<const float2*>(Wp + (size_t)(c0 + i) * LDW));
}
template<int U, int LDW>
__device__ __forceinline__ void ldg_w1(const float* __restrict__ Wp, int c0, float w[U]) {
#pragma unroll
    for (int i = 0; i < U; ++i)
        w[i] = __ldg(Wp + (size_t)(c0 + i) * LDW);
}

__device__ __forceinline__ void load_xs(const float* __restrict__ xb, u64 xs[ROWP]) {
    ulonglong2 x01 = *reinterpret_cast<const ulonglong2*>(xb);      // LDS.128 (broadcast)
    ulonglong2 x23 = *reinterpret_cast<const ulonglong2*>(xb + 4);
    ulonglong2 x45 = *reinterpret_cast<const ulonglong2*>(xb + 8);
    ulonglong2 x67 = *reinterpret_cast<const ulonglong2*>(xb + 12);
    u64 x8 = *reinterpret_cast<const u64*>(xb + 16);                // LDS.64
    xs[0] = x01.x; xs[1] = x01.y; xs[2] = x23.x; xs[3] = x23.y;
    xs[4] = x45.x; xs[5] = x45.y; xs[6] = x67.x; xs[7] = x67.y; xs[8] = x8;
}

template<int U>
__device__ __forceinline__ void comp2(const float* __restrict__ sXT, int c0,
                                      const float2 w[U], u64 acc[ROWP][2]) {
#pragma unroll
    for (int i = 0; i < U; ++i) {
        u64 w0 = pack2(w[i].x, w[i].x);
        u64 w1 = pack2(w[i].y, w[i].y);
        u64 xs[ROWP];
        load_xs(sXT + (c0 + i) * RPAD, xs);
#pragma unroll
        for (int rp = 0; rp < ROWP; ++rp) {
            acc[rp][0] = ffma2(xs[rp], w0, acc[rp][0]);
            acc[rp][1] = ffma2(xs[rp], w1, acc[rp][1]);
        }
    }
}
template<int U>
__device__ __forceinline__ void comp1(const float* __restrict__ sXT, int c0,
                                      const float w[U], u64 acc[ROWP][1]) {
#pragma unroll
    for (int i = 0; i < U; ++i) {
        u64 w0 = pack2(w[i], w[i]);
        u64 xs[ROWP];
        load_xs(sXT + (c0 + i) * RPAD, xs);
#pragma unroll
        for (int rp = 0; rp < ROWP; ++rp)
            acc[rp][0] = ffma2(xs[rp], w0, acc[rp][0]);
    }
}

// double-buffered cores: weights for group g+1 are in flight while group g computes
template<int CCH, int LDW, int U>
__device__ __forceinline__ void core2(const float* __restrict__ sXT,
                                      const float* __restrict__ Wp,
                                      u64 acc[ROWP][2]) {
    constexpr int G = CCH / U;
    static_assert(CCH % U == 0 && (G % 2) == 0, "pipeline shape");
    float2 wa[U], wb[U];
    ldg_w2<U, LDW>(Wp, 0, wa);
#pragma unroll 1
    for (int g = 0; g < G; g += 2) {
        ldg_w2<U, LDW>(Wp, (g + 1) * U, wb);
        comp2<U>(sXT, g * U, wa, acc);
        if (g + 2 < G) ldg_w2<U, LDW>(Wp, (g + 2) * U, wa);
        comp2<U>(sXT, (g + 1) * U, wb, acc);
    }
}
template<int CCH, int LDW, int U>
__device__ __forceinline__ void core1(const float* __restrict__ sXT,
                                      const float* __restrict__ Wp,
                                      u64 acc[ROWP][1]) {
    constexpr int G = CCH / U;
    static_assert(CCH % U == 0 && (G % 2) == 0, "pipeline shape");
    float wa[U], wb[U];
    ldg_w1<U, LDW>(Wp, 0, wa);
#pragma unroll 1
    for (int g = 0; g < G; g += 2) {
        ldg_w1<U, LDW>(Wp, (g + 1) * U, wb);
        comp1<U>(sXT, g * U, wa, acc);
        if (g + 2 < G) ldg_w1<U, LDW>(Wp, (g + 2) * U, wa);
        comp1<U>(sXT, (g + 1) * U, wb, acc);
    }
}

// raw partial store, 17 real rows, row stride N
template<int N, int CPT>
__device__ __forceinline__ void store_partial(u64 acc[ROWP][CPT], float* __restrict__ out) {
#pragma unroll
    for (int rp = 0; rp < ROWP; ++rp) {
        float2 c0 = unpack2(acc[rp][0]);
        if (CPT == 2) {
            float2 c1 = unpack2(acc[rp][1]);
            *reinterpret_cast<float2*>(out + (size_t)(2 * rp) * N) = make_float2(c0.x, c1.x);
            if (2 * rp + 1 < ROWS)
                *reinterpret_cast<float2*>(out + (size_t)(2 * rp + 1) * N) = make_float2(c0.y, c1.y);
        } else {
            out[(size_t)(2 * rp) * N] = c0.x;
            if (2 * rp + 1 < ROWS) out[(size_t)(2 * rp + 1) * N] = c0.y;
        }
    }
}

// ---------------- layer 1: gather + [17x312]@[312x1024], split-K x3 ----------------
__global__ void __launch_bounds__(128) l1_kernel(const float* __restrict__ v2s,
                                                 const int* __restrict__ tar,
                                                 const int* __restrict__ sidx,
                                                 const float* __restrict__ W1) {
    __shared__ __align__(16) float sXT[CCH1 * RPAD];
    __shared__ int sRow[ROWS];
    const int tid = threadIdx.x;
    const int cb = blockIdx.x % CB1;
    const int kc = (blockIdx.x / CB1) % KCH1;
    const int b  = blockIdx.x / (CB1 * KCH1);
    if (tid < ROWS) sRow[tid] = (tid == 0) ? b : sidx[b * KSAMP + tid - 1];
    __syncthreads();
    const int c0 = kc * CCH1;
    for (int idx = tid; idx < CCH1 * RPAD; idx += 128) {
        int r = idx / CCH1, c = idx - r * CCH1;
        sXT[c * RPAD + r] = (r < ROWS) ? v2s[(size_t)sRow[r] * D_IN + c0 + c] : 0.f;
    }
    __syncthreads();
    const int e = tar[b];
    const int j0 = (cb * 128 + tid) * 2;
    u64 acc[ROWP][2] = {};
    core2<CCH1, H1, U1>(sXT, W1 + ((size_t)e * D_IN + c0) * H1 + j0, acc);
    store_partial<H1, 2>(acc, g_h1p + (((size_t)kc * BATCH + b) * ROWS) * H1 + j0);
}

// ---------------- layer 2: [17x1024]@[1024x2048], split-K x4 ----------------
// input = relu(sum of 3 L1 partial slots + b1), built during smem fill
__global__ void __launch_bounds__(128) l2_kernel(const int* __restrict__ tar,
                                                 const float* __restrict__ W2,
                                                 const float* __restrict__ b1) {
    __shared__ __align__(16) float sXT[CCH2 * RPAD];   // 20 KB
    const int tid = threadIdx.x;
    const int cb = blockIdx.x % CB2;
    const int kc = (blockIdx.x / CB2) % KCH2;
    const int b  = blockIdx.x / (CB2 * KCH2);
    const int e  = tar[b];
    const int c0 = kc * CCH2;
    const size_t SL = (size_t)BATCH * ROWS * H1;
    for (int idx = tid; idx < CCH2 * RPAD; idx += 128) {
        int r = idx / CCH2, c = idx & (CCH2 - 1);
        float v = 0.f;
        if (r < ROWS) {
            int cg = c0 + c;
            size_t off = ((size_t)b * ROWS + r) * H1 + cg;
            float s = g_h1p[off] + g_h1p[SL + off] + g_h1p[2 * SL + off];
            v = fmaxf(s + b1[(size_t)e * H1 + cg], 0.f);
        }
        sXT[c * RPAD + r] = v;
    }
    __syncthreads();
    const int j0 = (cb * 128 + tid) * 2;
    u64 acc[ROWP][2] = {};
    core2<CCH2, H2, U2>(sXT, W2 + ((size_t)e * H1 + c0) * H2 + j0, acc);
    store_partial<H2, 2>(acc, g_h2p + (((size_t)kc * BATCH + b) * ROWS) * H2 + j0);
}

// ---------------- layer 3: [17x2048]@[2048x128], split-K x16 ----------------
// input = relu(sum of 4 L2 partial slots + b2), built during smem fill
__global__ void __launch_bounds__(128) l3_kernel(const int* __restrict__ tar,
                                                 const float* __restrict__ W3,
                                                 const float* __restrict__ b2) {
    __shared__ __align__(16) float sXT[CCH3 * RPAD];   // 10 KB
    const int tid = threadIdx.x;
    const int kc = blockIdx.x % KCH3;
    const int b  = blockIdx.x / KCH3;
    const int e  = tar[b];
    const int c0 = kc * CCH3;
    const size_t SL = (size_t)BATCH * ROWS * H2;
    for (int idx = tid; idx < CCH3 * RPAD; idx += 128) {
        int r = idx / CCH3, c = idx & (CCH3 - 1);
        float v = 0.f;
        if (r < ROWS) {
            int cg = c0 + c;
            size_t off = ((size_t)b * ROWS + r) * H2 + cg;
            float s = g_h2p[off] + g_h2p[SL + off] + g_h2p[2 * SL + off] + g_h2p[3 * SL + off];
            v = fmaxf(s + b2[(size_t)e * H2 + cg], 0.f);
        }
        sXT[c * RPAD + r] = v;
    }
    __syncthreads();
    u64 acc[ROWP][1] = {};
    core1<CCH3, D_OUT, U3>(sXT, W3 + ((size_t)e * H2 + c0) * D_OUT + tid, acc);
    store_partial<D_OUT, 1>(acc, g_p + (((size_t)kc * BATCH + b) * ROWS) * D_OUT + tid);
}

// ---------------- reduce 16 L3 partials + b3 + relu -> g_qk (one block per (b,row)) ----
__global__ void __launch_bounds__(128) reduce_kernel(const int* __restrict__ tar,
                                                     const float* __restrict__ b3) {
    const int b = blockIdx.x / ROWS;
    const int r = blockIdx.x % ROWS;
    const int c = threadIdx.x;             // one column each
    const int e = tar[b];
    const size_t SL = (size_t)BATCH * ROWS * D_OUT;
    const size_t off = ((size_t)b * ROWS + r) * D_OUT + c;
    float v = b3[(size_t)e * D_OUT + c];
#pragma unroll
    for (int s = 0; s < KCH3; ++s) v += g_p[s * SL + off];
    g_qk[off] = fmaxf(v, 0.f);
}

// ---------------- logits: dot(q, k) / T ----------------
__global__ void __launch_bounds__(256) logits_kernel(float* __restrict__ out) {
    __shared__ float sQK[ROWS * D_OUT];
    const int b = blockIdx.x;
    const int tid = threadIdx.x;
    const float* __restrict__ src = g_qk + (size_t)b * ROWS * D_OUT;
    for (int idx = tid; idx < ROWS * D_OUT; idx += 256) sQK[idx] = src[idx];
    __syncthreads();
    const int k = tid >> 4;                // 16 lanes per logit
    const int l = tid & 15;
    float s = 0.f;
#pragma unroll
    for (int j = 0; j < D_OUT / 16; ++j) {
        int col = l + j * 16;
        s += sQK[col] * sQK[(k + 1) * D_OUT + col];
    }
    s += __shfl_xor_sync(0xFFFFFFFFu, s, 1);
    s += __shfl_xor_sync(0xFFFFFFFFu, s, 2);
    s += __shfl_xor_sync(0xFFFFFFFFu, s, 4);
    s += __shfl_xor_sync(0xFFFFFFFFu, s, 8);
    if (l == 0) out[b * KSAMP + k] = s * INV_T;
}

// ---------------- launch ----------------
extern "C" void kernel_launch(void* const* d_in, const int* in_sizes, int n_in,
                              void* d_out, int out_size) {
    const float* v2s  = (const float*)d_in[0];
    const float* W1   = (const float*)d_in[1];
    const float* b1   = (const float*)d_in[2];
    const float* W2   = (const float*)d_in[3];
    const float* b2   = (const float*)d_in[4];
    const float* W3   = (const float*)d_in[5];
    const float* b3   = (const float*)d_in[6];
    const int*   tar  = (const int*)d_in[7];
    const int*   sidx = (const int*)d_in[8];
    float* out = (float*)d_out;

    l1_kernel<<<BATCH * KCH1 * CB1, 128>>>(v2s, tar, sidx, W1);   // 384 blocks
    l2_kernel<<<BATCH * KCH2 * CB2, 128>>>(tar, W2, b1);          // 1024 blocks
    l3_kernel<<<BATCH * KCH3, 128>>>(tar, W3, b2);                // 512 blocks
    reduce_kernel<<<BATCH * ROWS, 128>>>(tar, b3);                // 544 blocks
    logits_kernel<<<BATCH, 256>>>(out);                           // 32 blocks
}